// round 1
// baseline (speedup 1.0000x reference)
#include <cuda_runtime.h>
#include <math.h>

// Problem constants
#define PB 2
#define PL 2048
#define PD 1024
#define PH 16
#define PHD 64
#define PM (PB*PL)          // 4096 rows of X
#define PN3 (3*PD)          // 3072
#define PZH (PB*PH)         // 32 head-batches
#define OUT_ELEMS (PB*PL*PD)                     // 4194304
#define ATTN_ELEMS ((long long)PZH*PL*PL)        // 134217728

// Scratch (device globals: allocation-free rule)
__device__ float g_proj[PM*PN3];         // 50 MB
__device__ float g_q[PZH*PL*PHD];        // 16 MB
__device__ float g_k[PZH*PL*PHD];
__device__ float g_v[PZH*PL*PHD];
__device__ float g_ctxh[PZH*PL*PHD];
__device__ float g_ctx[PM*PD];
__device__ float g_attn[134217728];      // 536 MB fallback if attn not in d_out

// ---------------------------------------------------------------------------
// Generic batched SGEMM: C = A @ B (+ bias), row-major, tile-aligned dims.
// ---------------------------------------------------------------------------
template<int BM,int BN,int BK,int TM,int TN>
__global__ void __launch_bounds__(256) sgemm_kernel(
    const float* __restrict__ A, const float* __restrict__ Bm,
    const float* __restrict__ bias, float* __restrict__ C,
    int Mv, int Nv, int Kv,
    long long sA, long long sB, long long sC)
{
    __shared__ float As[BK][BM];
    __shared__ float Bs[BK][BN];
    constexpr int THREADS = (BM/TM)*(BN/TN);
    const int tid = threadIdx.x;
    A  += (long long)blockIdx.z * sA;
    Bm += (long long)blockIdx.z * sB;
    C  += (long long)blockIdx.z * sC;
    const int row0 = blockIdx.y * BM;
    const int col0 = blockIdx.x * BN;
    const int tx = tid % (BN/TN);
    const int ty = tid / (BN/TN);
    float acc[TM][TN] = {};

    constexpr int A_F4 = BK/4;                 // float4 per A-row slice
    const int a_r = tid / A_F4;
    const int a_c = (tid % A_F4) * 4;
    constexpr int A_STEP = THREADS / A_F4;
    constexpr int B_F4 = BN/4;
    const int b_r = tid / B_F4;
    const int b_c = (tid % B_F4) * 4;
    constexpr int B_STEP = THREADS / B_F4;

    for (int k0 = 0; k0 < Kv; k0 += BK) {
        #pragma unroll
        for (int r = a_r; r < BM; r += A_STEP) {
            float4 v = *(const float4*)&A[(long long)(row0 + r)*Kv + k0 + a_c];
            As[a_c+0][r] = v.x; As[a_c+1][r] = v.y;
            As[a_c+2][r] = v.z; As[a_c+3][r] = v.w;
        }
        #pragma unroll
        for (int r = b_r; r < BK; r += B_STEP) {
            *(float4*)&Bs[r][b_c] =
                *(const float4*)&Bm[(long long)(k0 + r)*Nv + col0 + b_c];
        }
        __syncthreads();
        #pragma unroll
        for (int kk = 0; kk < BK; kk++) {
            float ar[TM], br[TN];
            #pragma unroll
            for (int i = 0; i < TM; i++) ar[i] = As[kk][ty*TM+i];
            #pragma unroll
            for (int j = 0; j < TN; j++) br[j] = Bs[kk][tx*TN+j];
            #pragma unroll
            for (int i = 0; i < TM; i++)
                #pragma unroll
                for (int j = 0; j < TN; j++)
                    acc[i][j] += ar[i]*br[j];
        }
        __syncthreads();
    }
    #pragma unroll
    for (int i = 0; i < TM; i++) {
        const int r = row0 + ty*TM + i;
        #pragma unroll
        for (int j = 0; j < TN; j += 4) {
            const int c = col0 + tx*TN + j;
            float4 o;
            o.x = acc[i][j+0]; o.y = acc[i][j+1];
            o.z = acc[i][j+2]; o.w = acc[i][j+3];
            if (bias) {
                o.x += bias[c+0]; o.y += bias[c+1];
                o.z += bias[c+2]; o.w += bias[c+3];
            }
            *(float4*)&C[(long long)r*Nv + c] = o;
        }
    }
}

// ---------------------------------------------------------------------------
// Split heads: proj[B,L,3D] -> dense qh/kh/vh [ZH, L, HD] (no-transpose reshape)
//   i = z*131072 + l2*64 + d2 ;  row = (z>>4)*2048 + (z&15)*128 + (inner>>10)
//   col = inner & 1023
// ---------------------------------------------------------------------------
__global__ void split_heads_kernel(const float* __restrict__ proj,
                                   float* __restrict__ q,
                                   float* __restrict__ k,
                                   float* __restrict__ v)
{
    const int i4 = blockIdx.x * blockDim.x + threadIdx.x;   // float4 index
    const long long i = (long long)i4 * 4;
    const int inner = (int)(i & (PL*PHD - 1));
    const int z = (int)(i >> 17);
    const int row = (z >> 4)*PL + (z & 15)*128 + (inner >> 10);
    const int col = inner & (PD - 1);
    const long long base = (long long)row * PN3 + col;
    ((float4*)q)[i4] = *(const float4*)&proj[base];
    ((float4*)k)[i4] = *(const float4*)&proj[base + PD];
    ((float4*)v)[i4] = *(const float4*)&proj[base + 2*PD];
}

// ---------------------------------------------------------------------------
// Merge heads: ctxh [ZH, L, HD] -> ctx [B, L, D] (inverse reshape)
// ---------------------------------------------------------------------------
__global__ void merge_heads_kernel(const float* __restrict__ ctxh,
                                   float* __restrict__ ctx)
{
    const int i4 = blockIdx.x * blockDim.x + threadIdx.x;
    const long long i = (long long)i4 * 4;
    const int inner = (int)(i & (PL*PHD - 1));
    const int z = (int)(i >> 17);
    const int row = (z >> 4)*PL + (z & 15)*128 + (inner >> 10);
    const int col = inner & (PD - 1);
    *(float4*)&ctx[(long long)row*PD + col] = ((const float4*)ctxh)[i4];
}

// ---------------------------------------------------------------------------
// Scores: S[z, q, k] = (qh[z] @ kh[z]^T) * (1/32) * mask[q,k]
// A = qh (2048x64 rm), B = kh (2048x64 rm), K = 64.
// ---------------------------------------------------------------------------
template<int BM,int BN,int BK,int TM,int TN>
__global__ void __launch_bounds__(256) scores_kernel(
    const float* __restrict__ Q, const float* __restrict__ Kt,
    const float* __restrict__ mask, float* __restrict__ S)
{
    __shared__ float As[BK][BM];
    __shared__ float Bs[BK][BN];
    constexpr int THREADS = (BM/TM)*(BN/TN);
    const int tid = threadIdx.x;
    const int z = blockIdx.z;
    Q  += (long long)z * PL * PHD;
    Kt += (long long)z * PL * PHD;
    S  += (long long)z * PL * PL;
    const int row0 = blockIdx.y * BM;
    const int col0 = blockIdx.x * BN;
    const int tx = tid % (BN/TN);
    const int ty = tid / (BN/TN);
    float acc[TM][TN] = {};

    constexpr int F4 = BK/4;
    const int a_r = tid / F4;
    const int a_c = (tid % F4) * 4;
    constexpr int STEP = THREADS / F4;

    for (int k0 = 0; k0 < PHD; k0 += BK) {
        #pragma unroll
        for (int r = a_r; r < BM; r += STEP) {
            float4 v = *(const float4*)&Q[(long long)(row0 + r)*PHD + k0 + a_c];
            As[a_c+0][r]=v.x; As[a_c+1][r]=v.y; As[a_c+2][r]=v.z; As[a_c+3][r]=v.w;
        }
        #pragma unroll
        for (int r = a_r; r < BN; r += STEP) {
            float4 v = *(const float4*)&Kt[(long long)(col0 + r)*PHD + k0 + a_c];
            Bs[a_c+0][r]=v.x; Bs[a_c+1][r]=v.y; Bs[a_c+2][r]=v.z; Bs[a_c+3][r]=v.w;
        }
        __syncthreads();
        #pragma unroll
        for (int kk = 0; kk < BK; kk++) {
            float ar[TM], br[TN];
            #pragma unroll
            for (int i = 0; i < TM; i++) ar[i] = As[kk][ty*TM+i];
            #pragma unroll
            for (int j = 0; j < TN; j++) br[j] = Bs[kk][tx*TN+j];
            #pragma unroll
            for (int i = 0; i < TM; i++)
                #pragma unroll
                for (int j = 0; j < TN; j++)
                    acc[i][j] += ar[i]*br[j];
        }
        __syncthreads();
    }
    const float scale = 0.03125f;   // 1/sqrt(1024)
    #pragma unroll
    for (int i = 0; i < TM; i++) {
        const int r = row0 + ty*TM + i;
        #pragma unroll
        for (int j = 0; j < TN; j += 4) {
            const int c = col0 + tx*TN + j;
            float4 mv = *(const float4*)&mask[(long long)r*PL + c];
            float4 o;
            o.x = acc[i][j+0]*scale*mv.x;
            o.y = acc[i][j+1]*scale*mv.y;
            o.z = acc[i][j+2]*scale*mv.z;
            o.w = acc[i][j+3]*scale*mv.w;
            *(float4*)&S[(long long)r*PL + c] = o;
        }
    }
}

// ---------------------------------------------------------------------------
// In-place softmax over rows of length 2048.
// ---------------------------------------------------------------------------
__global__ void __launch_bounds__(256) softmax2048_kernel(float* __restrict__ data)
{
    __shared__ float buf[PL];
    __shared__ float red[256];
    float* row = data + (long long)blockIdx.x * PL;
    const int t = threadIdx.x;

    float m = -1e30f;
    #pragma unroll
    for (int i = t; i < PL; i += 256) { float v = row[i]; buf[i] = v; m = fmaxf(m, v); }
    red[t] = m; __syncthreads();
    #pragma unroll
    for (int s = 128; s > 0; s >>= 1) { if (t < s) red[t] = fmaxf(red[t], red[t+s]); __syncthreads(); }
    m = red[0];
    __syncthreads();

    float sum = 0.f;
    #pragma unroll
    for (int i = t; i < PL; i += 256) { float e = __expf(buf[i] - m); buf[i] = e; sum += e; }
    red[t] = sum; __syncthreads();
    #pragma unroll
    for (int s = 128; s > 0; s >>= 1) { if (t < s) red[t] += red[t+s]; __syncthreads(); }
    const float inv = 1.0f / red[0];
    #pragma unroll
    for (int i = t; i < PL; i += 256) row[i] = buf[i] * inv;
}

// ---------------------------------------------------------------------------
extern "C" void kernel_launch(void* const* d_in, const int* in_sizes, int n_in,
                              void* d_out, int out_size)
{
    const float* x    = (const float*)d_in[0];   // [B,L,D]
    const float* mask = (const float*)d_in[1];   // [1,1,L,L]
    const float* Wqkv = (const float*)d_in[2];   // [D,3D]
    const float* bqkv = (const float*)d_in[3];   // [3D]
    const float* Wout = (const float*)d_in[4];   // [D,D]
    const float* bout = (const float*)d_in[5];   // [D]
    float* out = (float*)d_out;

    float *proj, *q, *k, *v, *ctxh, *ctx, *attn_scratch;
    cudaGetSymbolAddress((void**)&proj, g_proj);
    cudaGetSymbolAddress((void**)&q,    g_q);
    cudaGetSymbolAddress((void**)&k,    g_k);
    cudaGetSymbolAddress((void**)&v,    g_v);
    cudaGetSymbolAddress((void**)&ctxh, g_ctxh);
    cudaGetSymbolAddress((void**)&ctx,  g_ctx);
    cudaGetSymbolAddress((void**)&attn_scratch, g_attn);

    // Does the harness expect attn appended after out?
    float* attn = ((long long)out_size >= (long long)OUT_ELEMS + ATTN_ELEMS)
                  ? out + OUT_ELEMS : attn_scratch;

    // 1) proj = X @ Wqkv + bqkv           [4096 x 3072], K=1024
    {
        dim3 g(PN3/128, PM/128, 1);
        sgemm_kernel<128,128,8,8,8><<<g, 256>>>(x, Wqkv, bqkv, proj,
                                                PM, PN3, PD, 0, 0, 0);
    }
    // 2) split into dense per-head q/k/v  [32 x 2048 x 64]
    split_heads_kernel<<<(PZH*PL*PHD/4)/256, 256>>>(proj, q, k, v);

    // 3) scores = (q @ k^T)/32 * mask     [32 x 2048 x 2048]
    {
        dim3 g(PL/128, PL/128, PZH);
        scores_kernel<128,128,8,8,8><<<g, 256>>>(q, k, mask, attn);
    }
    // 4) softmax rows (in place, also the attn output if requested)
    softmax2048_kernel<<<PZH*PL, 256>>>(attn);

    // 5) ctxh = attn @ v                  [32 x 2048 x 64], K=2048
    {
        dim3 g(PHD/64, PL/128, PZH);
        sgemm_kernel<128,64,16,8,4><<<g, 256>>>(attn, v, nullptr, ctxh,
                                                PL, PHD, PL,
                                                (long long)PL*PL,
                                                (long long)PL*PHD,
                                                (long long)PL*PHD);
    }
    // 6) merge heads -> ctx [B,L,D]
    merge_heads_kernel<<<(PZH*PL*PHD/4)/256, 256>>>(ctxh, ctx);

    // 7) out = ctx @ Wout + bout          [4096 x 1024], K=1024
    {
        dim3 g(PD/128, PM/128, 1);
        sgemm_kernel<128,128,8,8,8><<<g, 256>>>(ctx, Wout, bout, out,
                                                PM, PD, PD, 0, 0, 0);
    }
}

// round 5
// speedup vs baseline: 1.9820x; 1.9820x over previous
#include <cuda_runtime.h>
#include <math.h>

// Problem constants
#define PB 2
#define PL 2048
#define PD 1024
#define PH 16
#define PHD 64
#define PM (PB*PL)          // 4096
#define PN3 (3*PD)          // 3072
#define PZH (PB*PH)         // 32
#define OUT_ELEMS (PB*PL*PD)                     // 4194304
#define ATTN_ELEMS ((long long)PZH*PL*PL)        // 134217728

// Scratch (allocation-free rule: device globals)
__device__ float  g_q[PZH*PL*PHD];
__device__ float  g_k[PZH*PL*PHD];
__device__ float  g_v[PZH*PL*PHD];
__device__ float  g_ctx[PM*PD];
__device__ float2 g_stats[PZH*PL];
__device__ float  g_attn[134217728];   // fallback if attn not part of d_out

// ---------------------------------------------------------------------------
// helpers
// ---------------------------------------------------------------------------
__device__ __forceinline__ unsigned f2tf(float x){
    unsigned r; asm("cvt.rna.tf32.f32 %0, %1;" : "=r"(r) : "f"(x)); return r;
}
__device__ __forceinline__ void mma8(float* c, const unsigned* a, const unsigned* b){
    asm volatile("mma.sync.aligned.m16n8k8.row.col.f32.tf32.tf32.f32 "
        "{%0,%1,%2,%3}, {%4,%5,%6,%7}, {%8,%9}, {%0,%1,%2,%3};\n"
        : "+f"(c[0]),"+f"(c[1]),"+f"(c[2]),"+f"(c[3])
        : "r"(a[0]),"r"(a[1]),"r"(a[2]),"r"(a[3]), "r"(b[0]),"r"(b[1]));
}
__device__ __forceinline__ unsigned smem_u32(const void* p){
    return (unsigned)__cvta_generic_to_shared(p);
}
#define CP16(dst,src) asm volatile("cp.async.cg.shared.global [%0], [%1], 16;\n" :: "r"(dst), "l"(src))
#define CP_COMMIT()   asm volatile("cp.async.commit_group;\n")
#define CP_WAIT1()    asm volatile("cp.async.wait_group 1;\n")

// ---------------------------------------------------------------------------
// Generic TF32 GEMM, 128x128 tile, BK=16, cp.async double buffer, 256 thr.
// MODE 0: C = A@B + bias (row-major, ld=N)
// MODE 1: QKV: scatter into dense q/k/v [ZH][L][HD] (+bias) using the
//         reference's NO-TRANSPOSE reshape:
//           proj row r = b*2048 + lrow, col c = sel*1024 + cd
//           h  = lrow >> 7            (head comes from SEQUENCE position!)
//           l2 = (lrow & 127)*16 + (cd >> 6)
//           d  = cd & 63
// ---------------------------------------------------------------------------
template<int MODE>
__global__ void __launch_bounds__(256) gemm_tf32(
    const float* __restrict__ A, const float* __restrict__ B,
    const float* __restrict__ bias, float* __restrict__ C,
    int N, int K,
    float* __restrict__ qd, float* __restrict__ kd, float* __restrict__ vd)
{
    __shared__ float As[2][128][20];
    __shared__ float Bs[2][16][136];
    const int tid = threadIdx.x, lane = tid & 31, warp = tid >> 5;
    const int wm = warp >> 2, wn = warp & 3;          // 2 x 4 warps
    const int g = lane >> 2, t4 = lane & 3;
    const int row0 = blockIdx.y * 128, col0 = blockIdx.x * 128;
    float acc[4][4][4] = {};

    const int iters = K / 16;
    // prologue: tile 0 -> buf 0
    {
        #pragma unroll
        for (int p = 0; p < 2; p++){
            int idx = tid + p*256; int r = idx >> 2, kc = (idx & 3) << 2;
            CP16(smem_u32(&As[0][r][kc]), &A[(long long)(row0+r)*K + kc]);
        }
        #pragma unroll
        for (int p = 0; p < 2; p++){
            int idx = tid + p*256; int r = idx >> 5, c = (idx & 31) << 2;
            CP16(smem_u32(&Bs[0][r][c]), &B[(long long)r*N + col0 + c]);
        }
        CP_COMMIT();
    }
    for (int it = 0; it < iters; ++it){
        if (it + 1 < iters){
            const int k0 = (it+1)*16, nb = (it+1)&1;
            #pragma unroll
            for (int p = 0; p < 2; p++){
                int idx = tid + p*256; int r = idx >> 2, kc = (idx & 3) << 2;
                CP16(smem_u32(&As[nb][r][kc]), &A[(long long)(row0+r)*K + k0 + kc]);
            }
            #pragma unroll
            for (int p = 0; p < 2; p++){
                int idx = tid + p*256; int r = idx >> 5, c = (idx & 31) << 2;
                CP16(smem_u32(&Bs[nb][r][c]), &B[(long long)(k0+r)*N + col0 + c]);
            }
        }
        CP_COMMIT();
        CP_WAIT1();
        __syncthreads();
        const int b = it & 1;
        #pragma unroll
        for (int ks = 0; ks < 2; ks++){
            unsigned af[4][4], bf[4][2];
            #pragma unroll
            for (int mt = 0; mt < 4; mt++){
                int r = wm*64 + mt*16 + g;
                af[mt][0] = f2tf(As[b][r  ][ks*8 + t4  ]);
                af[mt][1] = f2tf(As[b][r+8][ks*8 + t4  ]);
                af[mt][2] = f2tf(As[b][r  ][ks*8 + t4+4]);
                af[mt][3] = f2tf(As[b][r+8][ks*8 + t4+4]);
            }
            #pragma unroll
            for (int nt = 0; nt < 4; nt++){
                int c = wn*32 + nt*8 + g;
                bf[nt][0] = f2tf(Bs[b][ks*8 + t4  ][c]);
                bf[nt][1] = f2tf(Bs[b][ks*8 + t4+4][c]);
            }
            #pragma unroll
            for (int mt = 0; mt < 4; mt++)
                #pragma unroll
                for (int nt = 0; nt < 4; nt++)
                    mma8(acc[mt][nt], af[mt], bf[nt]);
        }
        __syncthreads();
    }
    // epilogue
    #pragma unroll
    for (int mt = 0; mt < 4; mt++){
        #pragma unroll
        for (int nt = 0; nt < 4; nt++){
            const int r = row0 + wm*64 + mt*16 + g;
            const int c = col0 + wn*32 + nt*8 + t4*2;
            float bx = bias ? bias[c] : 0.f, by = bias ? bias[c+1] : 0.f;
            float v0 = acc[mt][nt][0] + bx, v1 = acc[mt][nt][1] + by;
            float v2 = acc[mt][nt][2] + bx, v3 = acc[mt][nt][3] + by;
            if (MODE == 0){
                float2 o0 = {v0, v1}, o1 = {v2, v3};
                *(float2*)&C[(long long)r*N + c]     = o0;
                *(float2*)&C[(long long)(r+8)*N + c] = o1;
            } else {
                // no-transpose reshape mapping (see header comment)
                const int sel = c >> 10, cd = c & 1023;
                const int d = cd & 63, csl = cd >> 6;
                float* dst = sel == 0 ? qd : (sel == 1 ? kd : vd);
                {
                    const int bb = r >> 11, lrow = r & 2047;
                    const int h = lrow >> 7, u = lrow & 127;
                    const int l2 = u*16 + csl;
                    long long off = ((long long)((bb*16 + h)*2048 + l2))*64 + d;
                    float2 o = {v0, v1}; *(float2*)&dst[off] = o;
                }
                {
                    const int r2 = r + 8;
                    const int bb = r2 >> 11, lrow = r2 & 2047;
                    const int h = lrow >> 7, u = lrow & 127;
                    const int l2 = u*16 + csl;
                    long long off = ((long long)((bb*16 + h)*2048 + l2))*64 + d;
                    float2 o = {v2, v3}; *(float2*)&dst[off] = o;
                }
            }
        }
    }
}

// ---------------------------------------------------------------------------
// Scores: S[z] = (Q[z] @ K[z]^T) * scale * mask   (raw, pre-softmax)
// 128x128 tile, K=64 in two BK=32 passes. TF32 mma.
// ---------------------------------------------------------------------------
__global__ void __launch_bounds__(256) scores_tf32(
    const float* __restrict__ Q, const float* __restrict__ Kh,
    const float* __restrict__ mask, float* __restrict__ S)
{
    __shared__ float As[128][36];
    __shared__ float Bs[32][136];
    const int z = blockIdx.z;
    Q  += (long long)z * PL * PHD;
    Kh += (long long)z * PL * PHD;
    S  += (long long)z * PL * PL;
    const int tid = threadIdx.x, lane = tid & 31, warp = tid >> 5;
    const int wm = warp >> 2, wn = warp & 3;
    const int g = lane >> 2, t4 = lane & 3;
    const int row0 = blockIdx.y * 128, col0 = blockIdx.x * 128;
    float acc[4][4][4] = {};

    #pragma unroll
    for (int k0 = 0; k0 < PHD; k0 += 32){
        __syncthreads();
        #pragma unroll
        for (int p = 0; p < 4; p++){
            int idx = tid + p*256; int r = idx >> 3, kc = (idx & 7) << 2;
            float4 a4 = *(const float4*)&Q[(long long)(row0+r)*PHD + k0 + kc];
            *(float4*)&As[r][kc] = a4;
            float4 b4 = *(const float4*)&Kh[(long long)(col0+r)*PHD + k0 + kc];
            Bs[kc  ][r] = b4.x; Bs[kc+1][r] = b4.y;
            Bs[kc+2][r] = b4.z; Bs[kc+3][r] = b4.w;
        }
        __syncthreads();
        #pragma unroll
        for (int ks = 0; ks < 4; ks++){
            unsigned af[4][4], bf[4][2];
            #pragma unroll
            for (int mt = 0; mt < 4; mt++){
                int r = wm*64 + mt*16 + g;
                af[mt][0] = f2tf(As[r  ][ks*8 + t4  ]);
                af[mt][1] = f2tf(As[r+8][ks*8 + t4  ]);
                af[mt][2] = f2tf(As[r  ][ks*8 + t4+4]);
                af[mt][3] = f2tf(As[r+8][ks*8 + t4+4]);
            }
            #pragma unroll
            for (int nt = 0; nt < 4; nt++){
                int c = wn*32 + nt*8 + g;
                bf[nt][0] = f2tf(Bs[ks*8 + t4  ][c]);
                bf[nt][1] = f2tf(Bs[ks*8 + t4+4][c]);
            }
            #pragma unroll
            for (int mt = 0; mt < 4; mt++)
                #pragma unroll
                for (int nt = 0; nt < 4; nt++)
                    mma8(acc[mt][nt], af[mt], bf[nt]);
        }
    }
    const float scale = 0.03125f;   // 1/sqrt(1024)
    #pragma unroll
    for (int mt = 0; mt < 4; mt++){
        #pragma unroll
        for (int nt = 0; nt < 4; nt++){
            const int r = row0 + wm*64 + mt*16 + g;
            const int c = col0 + wn*32 + nt*8 + t4*2;
            float2 m0 = *(const float2*)&mask[(long long)r*PL + c];
            float2 m1 = *(const float2*)&mask[(long long)(r+8)*PL + c];
            float2 o0 = {acc[mt][nt][0]*scale*m0.x, acc[mt][nt][1]*scale*m0.y};
            float2 o1 = {acc[mt][nt][2]*scale*m1.x, acc[mt][nt][3]*scale*m1.y};
            *(float2*)&S[(long long)r*PL + c]     = o0;
            *(float2*)&S[(long long)(r+8)*PL + c] = o1;
        }
    }
}

// ---------------------------------------------------------------------------
// Row stats: m = max(row), i = 1/sum(exp(row - m)). One warp per row.
// ---------------------------------------------------------------------------
__global__ void __launch_bounds__(256) stats_kernel(
    const float* __restrict__ S, float2* __restrict__ st)
{
    const int row  = blockIdx.x * 8 + (threadIdx.x >> 5);
    const int lane = threadIdx.x & 31;
    const float4* r = (const float4*)(S + (long long)row * PL);
    float4 v[16];
    float m = -1e30f;
    #pragma unroll
    for (int i = 0; i < 16; i++){
        v[i] = r[i*32 + lane];
        m = fmaxf(m, fmaxf(fmaxf(v[i].x, v[i].y), fmaxf(v[i].z, v[i].w)));
    }
    #pragma unroll
    for (int s = 16; s > 0; s >>= 1) m = fmaxf(m, __shfl_xor_sync(0xffffffffu, m, s));
    float sum = 0.f;
    #pragma unroll
    for (int i = 0; i < 16; i++){
        sum += __expf(v[i].x - m) + __expf(v[i].y - m)
             + __expf(v[i].z - m) + __expf(v[i].w - m);
    }
    #pragma unroll
    for (int s = 16; s > 0; s >>= 1) sum += __shfl_xor_sync(0xffffffffu, sum, s);
    if (lane == 0){ float2 o = {m, 1.f/sum}; st[row] = o; }
}

// ---------------------------------------------------------------------------
// Fused: attn = softmax(S) written in-place, ctx = attn @ V written directly
// into merged [B, L, D] layout. BM=128 rows, BN=64 (full hd), BK=32.
// ---------------------------------------------------------------------------
__global__ void __launch_bounds__(256) ctx_fused(
    float* __restrict__ S, const float* __restrict__ V,
    const float2* __restrict__ st, float* __restrict__ ctx)
{
    __shared__ float Ap[128][36];
    __shared__ float Vs[2][32][68];
    __shared__ float smax[128], sinv[128];
    const int z = blockIdx.y, row0 = blockIdx.x * 128;
    S += (long long)z * PL * PL;
    V += (long long)z * PL * PHD;
    const int tid = threadIdx.x, lane = tid & 31, warp = tid >> 5;
    const int wm = warp >> 1, wn = warp & 1;          // 4 x 2 warps: 32m x 32n
    const int g = lane >> 2, t4 = lane & 3;
    if (tid < 128){
        float2 t = st[z*PL + row0 + tid];
        smax[tid] = t.x; sinv[tid] = t.y;
    }
    float acc[2][4][4] = {};
    // prefetch V tile 0
    #pragma unroll
    for (int p = 0; p < 2; p++){
        int idx = tid + p*256; int r = idx >> 4, c = (idx & 15) << 2;
        CP16(smem_u32(&Vs[0][r][c]), &V[(long long)r*PHD + c]);
    }
    CP_COMMIT();
    __syncthreads();   // stats visible, Ap safe to write
    for (int it = 0; it < PL/32; ++it){
        const int k0 = it * 32;
        // load S tile, normalize, write attn (in place), stage into Ap
        #pragma unroll
        for (int p = 0; p < 4; p++){
            int idx = tid + p*256; int r = idx >> 3, kc = (idx & 7) << 2;
            long long off = (long long)(row0 + r)*PL + k0 + kc;
            float4 s4 = *(const float4*)&S[off];
            float mm = smax[r], ii = sinv[r];
            float4 pq;
            pq.x = __expf(s4.x - mm)*ii; pq.y = __expf(s4.y - mm)*ii;
            pq.z = __expf(s4.z - mm)*ii; pq.w = __expf(s4.w - mm)*ii;
            *(float4*)&S[off] = pq;
            *(float4*)&Ap[r][kc] = pq;
        }
        if (it + 1 < PL/32){
            const int nb = (it+1)&1, nk = (it+1)*32;
            #pragma unroll
            for (int p = 0; p < 2; p++){
                int idx = tid + p*256; int r = idx >> 4, c = (idx & 15) << 2;
                CP16(smem_u32(&Vs[nb][r][c]), &V[(long long)(nk+r)*PHD + c]);
            }
        }
        CP_COMMIT();
        CP_WAIT1();
        __syncthreads();
        const int b = it & 1;
        #pragma unroll
        for (int ks = 0; ks < 4; ks++){
            unsigned af[2][4], bf[4][2];
            #pragma unroll
            for (int mt = 0; mt < 2; mt++){
                int r = wm*32 + mt*16 + g;
                af[mt][0] = f2tf(Ap[r  ][ks*8 + t4  ]);
                af[mt][1] = f2tf(Ap[r+8][ks*8 + t4  ]);
                af[mt][2] = f2tf(Ap[r  ][ks*8 + t4+4]);
                af[mt][3] = f2tf(Ap[r+8][ks*8 + t4+4]);
            }
            #pragma unroll
            for (int nt = 0; nt < 4; nt++){
                int c = wn*32 + nt*8 + g;
                bf[nt][0] = f2tf(Vs[b][ks*8 + t4  ][c]);
                bf[nt][1] = f2tf(Vs[b][ks*8 + t4+4][c]);
            }
            #pragma unroll
            for (int mt = 0; mt < 2; mt++)
                #pragma unroll
                for (int nt = 0; nt < 4; nt++)
                    mma8(acc[mt][nt], af[mt], bf[nt]);
        }
        __syncthreads();
    }
    // epilogue: write ctx in merged [B,L,D] layout (no-transpose reshape inverse)
    const int bb = z >> 4, h = z & 15;
    #pragma unroll
    for (int mt = 0; mt < 2; mt++){
        #pragma unroll
        for (int nt = 0; nt < 4; nt++){
            const int l = row0 + wm*32 + mt*16 + g;
            const int d = wn*32 + nt*8 + t4*2;
            {
                int crow = bb*PL + h*128 + (l >> 4);
                int ccol = (l & 15)*64 + d;
                float2 o = {acc[mt][nt][0], acc[mt][nt][1]};
                *(float2*)&ctx[(long long)crow*PD + ccol] = o;
            }
            {
                int l2 = l + 8;
                int crow = bb*PL + h*128 + (l2 >> 4);
                int ccol = (l2 & 15)*64 + d;
                float2 o = {acc[mt][nt][2], acc[mt][nt][3]};
                *(float2*)&ctx[(long long)crow*PD + ccol] = o;
            }
        }
    }
}

// ---------------------------------------------------------------------------
extern "C" void kernel_launch(void* const* d_in, const int* in_sizes, int n_in,
                              void* d_out, int out_size)
{
    const float* x    = (const float*)d_in[0];
    const float* mask = (const float*)d_in[1];
    const float* Wqkv = (const float*)d_in[2];
    const float* bqkv = (const float*)d_in[3];
    const float* Wout = (const float*)d_in[4];
    const float* bout = (const float*)d_in[5];
    float* out = (float*)d_out;

    float *q, *k, *v, *ctx, *attn_scratch; float2* stats;
    cudaGetSymbolAddress((void**)&q,    g_q);
    cudaGetSymbolAddress((void**)&k,    g_k);
    cudaGetSymbolAddress((void**)&v,    g_v);
    cudaGetSymbolAddress((void**)&ctx,  g_ctx);
    cudaGetSymbolAddress((void**)&stats, g_stats);
    cudaGetSymbolAddress((void**)&attn_scratch, g_attn);

    float* attn = ((long long)out_size >= (long long)OUT_ELEMS + ATTN_ELEMS)
                  ? out + OUT_ELEMS : attn_scratch;

    // 1) QKV projection + head split (fused epilogue, no-transpose reshape)
    {
        dim3 grd(PN3/128, PM/128);
        gemm_tf32<1><<<grd, 256>>>(x, Wqkv, bqkv, nullptr, PN3, PD, q, k, v);
    }
    // 2) raw masked scores
    {
        dim3 grd(PL/128, PL/128, PZH);
        scores_tf32<<<grd, 256>>>(q, k, mask, attn);
    }
    // 3) per-row softmax stats
    stats_kernel<<<PZH*PL/8, 256>>>(attn, stats);
    // 4) fused normalize + attn write + attn@V -> merged ctx
    {
        dim3 grd(PL/128, PZH);
        ctx_fused<<<grd, 256>>>(attn, v, stats, ctx);
    }
    // 5) output projection
    {
        dim3 grd(PD/128, PM/128);
        gemm_tf32<0><<<grd, 256>>>(ctx, Wout, bout, out, PD, PD,
                                   nullptr, nullptr, nullptr);
    }
}